// round 15
// baseline (speedup 1.0000x reference)
#include <cuda_runtime.h>
#include <math.h>

#define NN   50000
#define EE   600000
#define HH   128
#define GG   50
#define NFF  128
#define LL   6
#define NCC  500
#define NMM  100
#define TEE  128   // edges per tile in edge kernel

// ---------------- scratch (device globals; no allocation allowed) ----------
__device__ float g_h[NN*HH];
__device__ float g_xf[NN*HH];
__device__ float g_agg[NN*HH];
__device__ float g_x1[NN*HH];
__device__ float g_d[EE];
__device__ float g_Cc[EE];
__device__ float g_conf[NCC*HH];
__device__ float g_mol[NMM*HH];

__device__ __forceinline__ float sspf(float x) {
    // shifted softplus: log(1+exp(x)) - log(2); t in (0,1] so __logf(1+t) is accurate
    float t = __expf(-fabsf(x));
    return fmaxf(x, 0.0f) + __logf(1.0f + t) - 0.69314718055994531f;
}

// 4-wide global reduction (sm_90+)
__device__ __forceinline__ void red_v4(float* addr, float a, float b, float c, float d) {
    asm volatile("red.global.add.v4.f32 [%0], {%1, %2, %3, %4};"
                 :: "l"(addr), "f"(a), "f"(b), "f"(c), "f"(d) : "memory");
}

// tf32 helpers
__device__ __forceinline__ float f2tf(float x) {
    unsigned r;
    asm("cvt.rna.tf32.f32 %0, %1;" : "=r"(r) : "f"(x));
    return __uint_as_float(r);
}
__device__ __forceinline__ void mma_tf32(float& c0, float& c1, float& c2, float& c3,
                                         unsigned a0, unsigned a1, unsigned a2, unsigned a3,
                                         unsigned b0, unsigned b1) {
    asm("mma.sync.aligned.m16n8k8.row.col.f32.tf32.tf32.f32 "
        "{%0,%1,%2,%3}, {%4,%5,%6,%7}, {%8,%9}, {%0,%1,%2,%3};"
        : "+f"(c0), "+f"(c1), "+f"(c2), "+f"(c3)
        : "r"(a0), "r"(a1), "r"(a2), "r"(a3), "r"(b0), "r"(b1));
}

// ---------------- embedding -------------------------------------------------
__global__ void embed_kernel(const int* __restrict__ z, const float* __restrict__ emb) {
    int idx = blockIdx.x * blockDim.x + threadIdx.x;
    if (idx < NN * HH) {
        g_h[idx] = emb[z[idx >> 7] * HH + (idx & 127)];
    }
}

// ---------------- edge geometry --------------------------------------------
__global__ void geom_kernel(const float* __restrict__ pos,
                            const int* __restrict__ er, const int* __restrict__ ec) {
    int e = blockIdx.x * blockDim.x + threadIdx.x;
    if (e < EE) {
        int r = er[e], c = ec[e];
        float dx = pos[3*r+0] - pos[3*c+0];
        float dy = pos[3*r+1] - pos[3*c+1];
        float dz = pos[3*r+2] - pos[3*c+2];
        float d = sqrtf(dx*dx + dy*dy + dz*dz);
        g_d[e]  = d;
        g_Cc[e] = 0.5f * (cosf(d * 0.31415926535897931f) + 1.0f);
    }
}

// ---------------- tensor-core node GEMM (tf32 mma) --------------------------
// out[m][n] = (ACT ? ssp(A[m][k]) : A[m][k]) @ W[k][n] (+bias[n]) (+res[m][n])
// 512 threads: 16 warps, each 32m x 32n. Full-K smem staging.
#define GT 512
#define GA_STRIDE 132
#define GW_STRIDE 136
#define GEMM_TC_SMEM ((128*GA_STRIDE + 128*GW_STRIDE + 128) * 4)

template<bool ACT, bool RES>
__global__ __launch_bounds__(GT, 1) void gemm_tc(
        const float* __restrict__ A, const float* __restrict__ W,
        const float* __restrict__ bias, const float* __restrict__ res,
        float* __restrict__ out, int M)
{
    extern __shared__ float smem[];
    float* sA = smem;                       // 128 x 132
    float* sW = smem + 128 * GA_STRIDE;     // 128 x 136
    float* sB = sW + 128 * GW_STRIDE;       // 128

    const int tid  = threadIdx.x;
    const int w    = tid >> 5;
    const int lane = tid & 31;
    const int gid  = lane >> 2;
    const int tid4 = lane & 3;
    const int m0   = blockIdx.x * 128;
    const int e0w  = (w >> 2) * 32;
    const int f0w  = (w & 3) * 32;

    // load A (with optional ssp), tf32
    for (int i = tid; i < 128 * 32; i += GT) {
        int m = i >> 5, q = (i & 31) * 4;
        float4 v = make_float4(0.f, 0.f, 0.f, 0.f);
        if (m0 + m < M) v = *(const float4*)&A[(size_t)(m0 + m) * 128 + q];
        if (ACT) { v.x = sspf(v.x); v.y = sspf(v.y); v.z = sspf(v.z); v.w = sspf(v.w); }
        v.x = f2tf(v.x); v.y = f2tf(v.y); v.z = f2tf(v.z); v.w = f2tf(v.w);
        *(float4*)&sA[m * GA_STRIDE + q] = v;
    }
    // load W, tf32
    for (int i = tid; i < 128 * 32; i += GT) {
        int k = i >> 5, q = (i & 31) * 4;
        float4 v = *(const float4*)&W[(size_t)k * 128 + q];
        v.x = f2tf(v.x); v.y = f2tf(v.y); v.z = f2tf(v.z); v.w = f2tf(v.w);
        *(float4*)&sW[k * GW_STRIDE + q] = v;
    }
    for (int i = tid; i < 128; i += GT) sB[i] = bias ? bias[i] : 0.0f;
    __syncthreads();

    float acc[2][4][4];
    #pragma unroll
    for (int mi = 0; mi < 2; mi++)
        #pragma unroll
        for (int ni = 0; ni < 4; ni++)
            #pragma unroll
            for (int q = 0; q < 4; q++) acc[mi][ni][q] = 0.0f;

    const unsigned* pA = (const unsigned*)sA;
    const unsigned* pW = (const unsigned*)sW;
    for (int kit = 0; kit < 16; kit++) {
        int kb = kit * 8;
        unsigned a[2][4];
        #pragma unroll
        for (int mi = 0; mi < 2; mi++) {
            int rb = e0w + mi * 16;
            a[mi][0] = pA[(rb + gid)     * GA_STRIDE + kb + tid4];
            a[mi][1] = pA[(rb + gid + 8) * GA_STRIDE + kb + tid4];
            a[mi][2] = pA[(rb + gid)     * GA_STRIDE + kb + tid4 + 4];
            a[mi][3] = pA[(rb + gid + 8) * GA_STRIDE + kb + tid4 + 4];
        }
        #pragma unroll
        for (int ni = 0; ni < 4; ni++) {
            int cb = f0w + ni * 8;
            unsigned bb0 = pW[(kb + tid4)     * GW_STRIDE + cb + gid];
            unsigned bb1 = pW[(kb + tid4 + 4) * GW_STRIDE + cb + gid];
            mma_tf32(acc[0][ni][0], acc[0][ni][1], acc[0][ni][2], acc[0][ni][3],
                     a[0][0], a[0][1], a[0][2], a[0][3], bb0, bb1);
            mma_tf32(acc[1][ni][0], acc[1][ni][1], acc[1][ni][2], acc[1][ni][3],
                     a[1][0], a[1][1], a[1][2], a[1][3], bb0, bb1);
        }
    }

    // epilogue: bias / residual / store
    #pragma unroll
    for (int mi = 0; mi < 2; mi++) {
        int r0 = e0w + mi * 16 + gid, r1 = r0 + 8;
        int gm0 = m0 + r0, gm1 = m0 + r1;
        #pragma unroll
        for (int ni = 0; ni < 4; ni++) {
            int cb = f0w + ni * 8 + 2 * tid4;
            float vb0 = sB[cb], vb1 = sB[cb + 1];
            if (gm0 < M) {
                float o0 = acc[mi][ni][0] + vb0;
                float o1 = acc[mi][ni][1] + vb1;
                if (RES) { o0 += res[(size_t)gm0 * 128 + cb]; o1 += res[(size_t)gm0 * 128 + cb + 1]; }
                *(float2*)&out[(size_t)gm0 * 128 + cb] = make_float2(o0, o1);
            }
            if (gm1 < M) {
                float o2 = acc[mi][ni][2] + vb0;
                float o3 = acc[mi][ni][3] + vb1;
                if (RES) { o2 += res[(size_t)gm1 * 128 + cb]; o3 += res[(size_t)gm1 * 128 + cb + 1]; }
                *(float2*)&out[(size_t)gm1 * 128 + cb] = make_float2(o2, o3);
            }
        }
    }
}

// ---------------- fused edge kernel (tensor-core MLP, 512 threads) ----------
#define SW1_OFF 0
#define SW2_OFF 7616
#define SB1_OFF 25024
#define SB2_OFF 25152
#define SG_OFF  25280
#define ST_OFF  32960
#define EDGE_SMEM_FLOATS 49856
#define ETHREADS 512

__global__ __launch_bounds__(ETHREADS, 1) void edge_kernel(
        const float* __restrict__ w1, const float* __restrict__ b1,
        const float* __restrict__ w2, const float* __restrict__ b2,
        const int* __restrict__ erow, const int* __restrict__ ecol,
        const float* __restrict__ xf, float* __restrict__ agg)
{
    extern __shared__ float sm[];
    float* s_w1 = sm + SW1_OFF;
    float* s_w2 = sm + SW2_OFF;
    float* s_b1 = sm + SB1_OFF;
    float* s_b2 = sm + SB2_OFF;
    float* s_g  = sm + SG_OFF;
    float* s_t  = sm + ST_OFF;

    const int tid  = threadIdx.x;
    const int w    = tid >> 5;
    const int lane = tid & 31;
    const int gid  = lane >> 2;       // 0..7
    const int tid4 = lane & 3;        // 0..3
    const int e0w  = (w >> 2) * 32;   // 16 warps: 4 row-blocks of 32 e
    const int f0w  = (w & 3) * 32;    //           4 col-blocks of 32 f

    // ---- one-time init: weights (tf32) + biases into smem ----
    for (int i = tid; i < GG * NFF; i += ETHREADS) {
        int g = i >> 7, f = i & 127;
        s_w1[g * 136 + f] = f2tf(w1[i]);
    }
    for (int i = tid; i < 6 * 136; i += ETHREADS) s_w1[GG * 136 + i] = 0.0f;
    for (int i = tid; i < NFF * NFF; i += ETHREADS) {
        int k = i >> 7, f = i & 127;
        s_w2[k * 136 + f] = f2tf(w2[i]);
    }
    for (int i = tid; i < 128; i += ETHREADS) { s_b1[i] = b1[i]; s_b2[i] = b2[i]; }

    // warp-coherent scatter constants: warp handles 8 edges, lane covers 4 features
    const int fsc = lane * 4;
    float b2f[4];
    __syncthreads();
    #pragma unroll
    for (int j = 0; j < 4; j++) b2f[j] = s_b2[fsc + j];

    const int ntiles = (EE + TEE - 1) / TEE;
    for (int t = blockIdx.x; t < ntiles; t += gridDim.x) {
        int base = t * TEE;

        // ---- stage A: Gaussian smearing -> s_g[e][g] (tf32), cols >=50 zero ----
        for (int i = tid; i < 56 * TEE; i += ETHREADS) {
            int e = i & 127, g = i >> 7;
            float v = 0.0f;
            if (g < GG) {
                int ge = base + e;
                float d = (ge < EE) ? g_d[ge] : 1.0e9f;  // exp -> 0 for pad
                float dd = d - (float)g * (10.0f / 49.0f);
                v = f2tf(__expf(-12.005f * dd * dd));
            }
            s_g[e * 60 + g] = v;
        }
        __syncthreads();

        // ---- stage B (mma): P = gauss @ w1 ; t1 = ssp(P + b1) -> s_t[e][f] tf32 ----
        {
            float acc[2][4][4];
            #pragma unroll
            for (int mi = 0; mi < 2; mi++)
                #pragma unroll
                for (int ni = 0; ni < 4; ni++)
                    #pragma unroll
                    for (int q = 0; q < 4; q++) acc[mi][ni][q] = 0.0f;

            const unsigned* pG  = (const unsigned*)s_g;
            const unsigned* pW1 = (const unsigned*)s_w1;
            for (int kit = 0; kit < 7; kit++) {
                int kb = kit * 8;
                unsigned a[2][4];
                #pragma unroll
                for (int mi = 0; mi < 2; mi++) {
                    int rb = e0w + mi * 16;
                    a[mi][0] = pG[(rb + gid)     * 60 + kb + tid4];
                    a[mi][1] = pG[(rb + gid + 8) * 60 + kb + tid4];
                    a[mi][2] = pG[(rb + gid)     * 60 + kb + tid4 + 4];
                    a[mi][3] = pG[(rb + gid + 8) * 60 + kb + tid4 + 4];
                }
                #pragma unroll
                for (int ni = 0; ni < 4; ni++) {
                    int cb = f0w + ni * 8;
                    unsigned bb0 = pW1[(kb + tid4)     * 136 + cb + gid];
                    unsigned bb1 = pW1[(kb + tid4 + 4) * 136 + cb + gid];
                    mma_tf32(acc[0][ni][0], acc[0][ni][1], acc[0][ni][2], acc[0][ni][3],
                             a[0][0], a[0][1], a[0][2], a[0][3], bb0, bb1);
                    mma_tf32(acc[1][ni][0], acc[1][ni][1], acc[1][ni][2], acc[1][ni][3],
                             a[1][0], a[1][1], a[1][2], a[1][3], bb0, bb1);
                }
            }
            // epilogue: ssp + bias, tf32, write s_t[e][f]
            #pragma unroll
            for (int mi = 0; mi < 2; mi++) {
                int r0 = e0w + mi * 16 + gid, r1 = r0 + 8;
                #pragma unroll
                for (int ni = 0; ni < 4; ni++) {
                    int cb = f0w + ni * 8 + 2 * tid4;
                    float vb0 = s_b1[cb], vb1 = s_b1[cb + 1];
                    float2 v0, v1;
                    v0.x = f2tf(sspf(acc[mi][ni][0] + vb0));
                    v0.y = f2tf(sspf(acc[mi][ni][1] + vb1));
                    v1.x = f2tf(sspf(acc[mi][ni][2] + vb0));
                    v1.y = f2tf(sspf(acc[mi][ni][3] + vb1));
                    *(float2*)&s_t[r0 * 132 + cb] = v0;
                    *(float2*)&s_t[r1 * 132 + cb] = v1;
                }
            }
        }
        __syncthreads();

        // ---- stage C (mma): P = t1 @ w2 ----
        {
            float acc[2][4][4];
            #pragma unroll
            for (int mi = 0; mi < 2; mi++)
                #pragma unroll
                for (int ni = 0; ni < 4; ni++)
                    #pragma unroll
                    for (int q = 0; q < 4; q++) acc[mi][ni][q] = 0.0f;

            const unsigned* pT  = (const unsigned*)s_t;
            const unsigned* pW2 = (const unsigned*)s_w2;
            for (int kit = 0; kit < 16; kit++) {
                int kb = kit * 8;
                unsigned a[2][4];
                #pragma unroll
                for (int mi = 0; mi < 2; mi++) {
                    int rb = e0w + mi * 16;
                    a[mi][0] = pT[(rb + gid)     * 132 + kb + tid4];
                    a[mi][1] = pT[(rb + gid + 8) * 132 + kb + tid4];
                    a[mi][2] = pT[(rb + gid)     * 132 + kb + tid4 + 4];
                    a[mi][3] = pT[(rb + gid + 8) * 132 + kb + tid4 + 4];
                }
                #pragma unroll
                for (int ni = 0; ni < 4; ni++) {
                    int cb = f0w + ni * 8;
                    unsigned bb0 = pW2[(kb + tid4)     * 136 + cb + gid];
                    unsigned bb1 = pW2[(kb + tid4 + 4) * 136 + cb + gid];
                    mma_tf32(acc[0][ni][0], acc[0][ni][1], acc[0][ni][2], acc[0][ni][3],
                             a[0][0], a[0][1], a[0][2], a[0][3], bb0, bb1);
                    mma_tf32(acc[1][ni][0], acc[1][ni][1], acc[1][ni][2], acc[1][ni][3],
                             a[1][0], a[1][1], a[1][2], a[1][3], bb0, bb1);
                }
            }
            __syncthreads();   // all warps done reading s_t before overwriting it with P
            #pragma unroll
            for (int mi = 0; mi < 2; mi++) {
                int r0 = e0w + mi * 16 + gid, r1 = r0 + 8;
                #pragma unroll
                for (int ni = 0; ni < 4; ni++) {
                    int cb = f0w + ni * 8 + 2 * tid4;
                    *(float2*)&s_t[r0 * 132 + cb] = make_float2(acc[mi][ni][0], acc[mi][ni][1]);
                    *(float2*)&s_t[r1 * 132 + cb] = make_float2(acc[mi][ni][2], acc[mi][ni][3]);
                }
            }
        }
        __syncthreads();

        // ---- scatter (warp-coherent): warp owns 8 edges, lane owns 4 features ----
        // per edge: broadcast indices, coalesced 512B xf row read, coalesced red_v4
        #pragma unroll
        for (int ei = 0; ei < 8; ei++) {
            int le = w * 8 + ei;         // local edge 0..127
            int e  = base + le;
            if (e < EE) {
                int r = erow[e], c = ecol[e];  // warp-uniform -> broadcast
                float Ce = g_Cc[e];
                float4 xv = *(const float4*)&xf[r * 128 + fsc];
                float4 p  = *(const float4*)&s_t[le * 132 + fsc];
                float m0 = (p.x + b2f[0]) * Ce * xv.x;
                float m1 = (p.y + b2f[1]) * Ce * xv.y;
                float m2 = (p.z + b2f[2]) * Ce * xv.z;
                float m3 = (p.w + b2f[3]) * Ce * xv.w;
                red_v4(&agg[c * 128 + fsc], m0, m1, m2, m3);
            }
        }
        // scatter precedes next stage A; post-A __syncthreads orders the s_t
        // readers here against the next tile's stage-B writers.
    }
}

// ---------------- pooling ---------------------------------------------------
__global__ void pool1_kernel(const int* __restrict__ a2c, const float* __restrict__ h2) {
    int idx = blockIdx.x * blockDim.x + threadIdx.x;  // over NN*32 quads
    if (idx < NN * 32) {
        int n = idx >> 5, q = (idx & 31) * 4;
        float4 v = *(const float4*)&h2[n * 128 + q];
        red_v4(&g_conf[a2c[n] * 128 + q], v.x, v.y, v.z, v.w);
    }
}
__global__ void pool2_kernel(const int* __restrict__ c2m) {
    int idx = blockIdx.x * blockDim.x + threadIdx.x;  // over NCC*32 quads
    if (idx < NCC * 32) {
        int n = idx >> 5, q = (idx & 31) * 4;
        float4 v = *(const float4*)&g_conf[n * 128 + q];
        red_v4(&g_mol[c2m[n] * 128 + q], v.x, v.y, v.z, v.w);
    }
}

// ---------------- head ------------------------------------------------------
__global__ void head_kernel(const float* __restrict__ w1, const float* __restrict__ b1_,
                            const float* __restrict__ w2, const float* __restrict__ b2_,
                            float* __restrict__ out) {
    __shared__ float red[2];
    int m = blockIdx.x, f = threadIdx.x;  // 64 threads
    float s = b1_[f];
    #pragma unroll 4
    for (int k = 0; k < 128; k++)
        s = fmaf(g_mol[m * 128 + k], w1[k * 64 + f], s);
    float v = sspf(s) * w2[f];
    #pragma unroll
    for (int o = 16; o; o >>= 1) v += __shfl_xor_sync(0xffffffffu, v, o);
    if ((f & 31) == 0) red[f >> 5] = v;
    __syncthreads();
    if (f == 0) out[m] = red[0] + red[1] + b2_[0];
}

// ---------------- launch ----------------------------------------------------
extern "C" void kernel_launch(void* const* d_in, const int* in_sizes, int n_in,
                              void* d_out, int out_size) {
    const int*   z    = (const int*)  d_in[0];
    const float* pos  = (const float*)d_in[1];
    const int*   erow = (const int*)  d_in[2];
    const int*   ecol = (const int*)  d_in[3];
    const int*   a2c  = (const int*)  d_in[4];
    const int*   c2m  = (const int*)  d_in[5];
    const float* emb  = (const float*)d_in[6];
    const float* mw1  = (const float*)d_in[7];
    const float* mb1  = (const float*)d_in[8];
    const float* mw2  = (const float*)d_in[9];
    const float* mb2  = (const float*)d_in[10];
    const float* cl1  = (const float*)d_in[11];
    const float* cl2  = (const float*)d_in[12];
    const float* cl2b = (const float*)d_in[13];
    const float* ilw  = (const float*)d_in[14];
    const float* ilb  = (const float*)d_in[15];
    const float* l1w  = (const float*)d_in[16];
    const float* l1b  = (const float*)d_in[17];
    const float* l2w  = (const float*)d_in[18];
    const float* l2b  = (const float*)d_in[19];
    const float* hw1  = (const float*)d_in[20];
    const float* hb1  = (const float*)d_in[21];
    const float* hw2  = (const float*)d_in[22];
    const float* hb2  = (const float*)d_in[23];
    float* out = (float*)d_out;

    const int EDGE_SMEM = EDGE_SMEM_FLOATS * 4;  // 199424 B
    cudaFuncSetAttribute(edge_kernel, cudaFuncAttributeMaxDynamicSharedMemorySize, EDGE_SMEM);
    cudaFuncSetAttribute(gemm_tc<false, false>, cudaFuncAttributeMaxDynamicSharedMemorySize, GEMM_TC_SMEM);
    cudaFuncSetAttribute(gemm_tc<true, true>,  cudaFuncAttributeMaxDynamicSharedMemorySize, GEMM_TC_SMEM);
    cudaFuncSetAttribute(gemm_tc<true, false>, cudaFuncAttributeMaxDynamicSharedMemorySize, GEMM_TC_SMEM);

    float *ph, *pxf, *pagg, *px1, *pconf, *pmol;
    cudaGetSymbolAddress((void**)&ph,   g_h);
    cudaGetSymbolAddress((void**)&pxf,  g_xf);
    cudaGetSymbolAddress((void**)&pagg, g_agg);
    cudaGetSymbolAddress((void**)&px1,  g_x1);
    cudaGetSymbolAddress((void**)&pconf, g_conf);
    cudaGetSymbolAddress((void**)&pmol,  g_mol);

    const int GEMM_BLOCKS = (NN + 127) / 128;  // 391

    embed_kernel<<<(NN * HH + 255) / 256, 256>>>(z, emb);
    geom_kernel<<<(EE + 255) / 256, 256>>>(pos, erow, ecol);

    for (int i = 0; i < LL; i++) {
        gemm_tc<false, false><<<GEMM_BLOCKS, GT, GEMM_TC_SMEM>>>(ph, cl1 + (size_t)i * HH * NFF,
                                                                 nullptr, nullptr, pxf, NN);
        cudaMemsetAsync(pagg, 0, (size_t)NN * HH * sizeof(float));
        edge_kernel<<<152, ETHREADS, EDGE_SMEM>>>(mw1 + (size_t)i * GG * NFF,
                                                  mb1 + (size_t)i * NFF,
                                                  mw2 + (size_t)i * NFF * NFF,
                                                  mb2 + (size_t)i * NFF,
                                                  erow, ecol, pxf, pagg);
        gemm_tc<false, false><<<GEMM_BLOCKS, GT, GEMM_TC_SMEM>>>(pagg, cl2 + (size_t)i * NFF * HH,
                                                                 cl2b + (size_t)i * HH, nullptr, px1, NN);
        gemm_tc<true, true><<<GEMM_BLOCKS, GT, GEMM_TC_SMEM>>>(px1, ilw + (size_t)i * HH * HH,
                                                               ilb + (size_t)i * HH, ph, ph, NN);
    }

    gemm_tc<false, false><<<GEMM_BLOCKS, GT, GEMM_TC_SMEM>>>(ph, l1w, l1b, nullptr, px1, NN);
    gemm_tc<true, false><<<GEMM_BLOCKS, GT, GEMM_TC_SMEM>>>(px1, l2w, l2b, nullptr, pxf, NN);

    cudaMemsetAsync(pconf, 0, (size_t)NCC * HH * sizeof(float));
    cudaMemsetAsync(pmol,  0, (size_t)NMM * HH * sizeof(float));
    pool1_kernel<<<(NN * 32 + 255) / 256, 256>>>(a2c, pxf);
    pool2_kernel<<<(NCC * 32 + 255) / 256, 256>>>(c2m);
    head_kernel<<<NMM, 64>>>(hw1, hb1, hw2, hb2, out);
}

// round 16
// speedup vs baseline: 1.1676x; 1.1676x over previous
#include <cuda_runtime.h>
#include <math.h>

#define NN   50000
#define EE   600000
#define HH   128
#define GG   50
#define NFF  128
#define LL   6
#define NCC  500
#define NMM  100
#define TEE  128   // edges per tile in edge kernel

// ---------------- scratch (device globals; no allocation allowed) ----------
__device__ float g_h[NN*HH];
__device__ float g_xf[NN*HH];
__device__ float g_agg[NN*HH];
__device__ float g_d[EE];
__device__ float g_Cc[EE];
__device__ float g_conf[NCC*HH];
__device__ float g_mol[NMM*HH];

__device__ __forceinline__ float sspf(float x) {
    // shifted softplus: log(1+exp(x)) - log(2); t in (0,1] so __logf(1+t) is accurate
    float t = __expf(-fabsf(x));
    return fmaxf(x, 0.0f) + __logf(1.0f + t) - 0.69314718055994531f;
}

// 4-wide global reduction (sm_90+)
__device__ __forceinline__ void red_v4(float* addr, float a, float b, float c, float d) {
    asm volatile("red.global.add.v4.f32 [%0], {%1, %2, %3, %4};"
                 :: "l"(addr), "f"(a), "f"(b), "f"(c), "f"(d) : "memory");
}

// tf32 helpers
__device__ __forceinline__ float f2tf(float x) {
    unsigned r;
    asm("cvt.rna.tf32.f32 %0, %1;" : "=r"(r) : "f"(x));
    return __uint_as_float(r);
}
__device__ __forceinline__ void mma_tf32(float& c0, float& c1, float& c2, float& c3,
                                         unsigned a0, unsigned a1, unsigned a2, unsigned a3,
                                         unsigned b0, unsigned b1) {
    asm("mma.sync.aligned.m16n8k8.row.col.f32.tf32.tf32.f32 "
        "{%0,%1,%2,%3}, {%4,%5,%6,%7}, {%8,%9}, {%0,%1,%2,%3};"
        : "+f"(c0), "+f"(c1), "+f"(c2), "+f"(c3)
        : "r"(a0), "r"(a1), "r"(a2), "r"(a3), "r"(b0), "r"(b1));
}

// ---------------- embedding -------------------------------------------------
__global__ void embed_kernel(const int* __restrict__ z, const float* __restrict__ emb) {
    int idx = blockIdx.x * blockDim.x + threadIdx.x;
    if (idx < NN * HH) {
        g_h[idx] = emb[z[idx >> 7] * HH + (idx & 127)];
    }
}

// ---------------- edge geometry --------------------------------------------
__global__ void geom_kernel(const float* __restrict__ pos,
                            const int* __restrict__ er, const int* __restrict__ ec) {
    int e = blockIdx.x * blockDim.x + threadIdx.x;
    if (e < EE) {
        int r = er[e], c = ec[e];
        float dx = pos[3*r+0] - pos[3*c+0];
        float dy = pos[3*r+1] - pos[3*c+1];
        float dz = pos[3*r+2] - pos[3*c+2];
        float d = sqrtf(dx*dx + dy*dy + dz*dz);
        g_d[e]  = d;
        g_Cc[e] = 0.5f * (cosf(d * 0.31415926535897931f) + 1.0f);
    }
}

// ---------------- tensor-core node GEMM (tf32 mma) --------------------------
// out[m][n] = A[m][k] @ W[k][n]   (no act/bias/res variant used for cl1 only)
#define GT 512
#define GA_STRIDE 132
#define GW_STRIDE 136
#define GEMM_TC_SMEM ((128*GA_STRIDE + 128*GW_STRIDE + 128) * 4)

__global__ __launch_bounds__(GT, 1) void gemm_tc(
        const float* __restrict__ A, const float* __restrict__ W,
        float* __restrict__ out, int M)
{
    extern __shared__ float smem[];
    float* sA = smem;                       // 128 x 132
    float* sW = smem + 128 * GA_STRIDE;     // 128 x 136

    const int tid  = threadIdx.x;
    const int w    = tid >> 5;
    const int lane = tid & 31;
    const int gid  = lane >> 2;
    const int tid4 = lane & 3;
    const int m0   = blockIdx.x * 128;
    const int e0w  = (w >> 2) * 32;
    const int f0w  = (w & 3) * 32;

    for (int i = tid; i < 128 * 32; i += GT) {
        int m = i >> 5, q = (i & 31) * 4;
        float4 v = make_float4(0.f, 0.f, 0.f, 0.f);
        if (m0 + m < M) v = *(const float4*)&A[(size_t)(m0 + m) * 128 + q];
        v.x = f2tf(v.x); v.y = f2tf(v.y); v.z = f2tf(v.z); v.w = f2tf(v.w);
        *(float4*)&sA[m * GA_STRIDE + q] = v;
    }
    for (int i = tid; i < 128 * 32; i += GT) {
        int k = i >> 5, q = (i & 31) * 4;
        float4 v = *(const float4*)&W[(size_t)k * 128 + q];
        v.x = f2tf(v.x); v.y = f2tf(v.y); v.z = f2tf(v.z); v.w = f2tf(v.w);
        *(float4*)&sW[k * GW_STRIDE + q] = v;
    }
    __syncthreads();

    float acc[2][4][4];
    #pragma unroll
    for (int mi = 0; mi < 2; mi++)
        #pragma unroll
        for (int ni = 0; ni < 4; ni++)
            #pragma unroll
            for (int q = 0; q < 4; q++) acc[mi][ni][q] = 0.0f;

    const unsigned* pA = (const unsigned*)sA;
    const unsigned* pW = (const unsigned*)sW;
    for (int kit = 0; kit < 16; kit++) {
        int kb = kit * 8;
        unsigned a[2][4];
        #pragma unroll
        for (int mi = 0; mi < 2; mi++) {
            int rb = e0w + mi * 16;
            a[mi][0] = pA[(rb + gid)     * GA_STRIDE + kb + tid4];
            a[mi][1] = pA[(rb + gid + 8) * GA_STRIDE + kb + tid4];
            a[mi][2] = pA[(rb + gid)     * GA_STRIDE + kb + tid4 + 4];
            a[mi][3] = pA[(rb + gid + 8) * GA_STRIDE + kb + tid4 + 4];
        }
        #pragma unroll
        for (int ni = 0; ni < 4; ni++) {
            int cb = f0w + ni * 8;
            unsigned bb0 = pW[(kb + tid4)     * GW_STRIDE + cb + gid];
            unsigned bb1 = pW[(kb + tid4 + 4) * GW_STRIDE + cb + gid];
            mma_tf32(acc[0][ni][0], acc[0][ni][1], acc[0][ni][2], acc[0][ni][3],
                     a[0][0], a[0][1], a[0][2], a[0][3], bb0, bb1);
            mma_tf32(acc[1][ni][0], acc[1][ni][1], acc[1][ni][2], acc[1][ni][3],
                     a[1][0], a[1][1], a[1][2], a[1][3], bb0, bb1);
        }
    }

    #pragma unroll
    for (int mi = 0; mi < 2; mi++) {
        int r0 = e0w + mi * 16 + gid, r1 = r0 + 8;
        int gm0 = m0 + r0, gm1 = m0 + r1;
        #pragma unroll
        for (int ni = 0; ni < 4; ni++) {
            int cb = f0w + ni * 8 + 2 * tid4;
            if (gm0 < M)
                *(float2*)&out[(size_t)gm0 * 128 + cb] = make_float2(acc[mi][ni][0], acc[mi][ni][1]);
            if (gm1 < M)
                *(float2*)&out[(size_t)gm1 * 128 + cb] = make_float2(acc[mi][ni][2], acc[mi][ni][3]);
        }
    }
}

// ---------------- fused double GEMM (tf32 mma) -------------------------------
// P1 = A @ W1 + b1 ; t = ssp(P1) ; out = t @ W2 + b2 (+ res if RES2)
// smem: sA 128x132 (A then t), sW1 128x136, sW2 128x136, biases
#define GEMM2_SMEM ((128*GA_STRIDE + 2*128*GW_STRIDE + 256) * 4)

template<bool RES2>
__global__ __launch_bounds__(GT, 1) void gemm2_tc(
        const float* __restrict__ A,
        const float* __restrict__ W1, const float* __restrict__ b1,
        const float* __restrict__ W2, const float* __restrict__ b2,
        const float* __restrict__ res, float* __restrict__ out, int M)
{
    extern __shared__ float smem[];
    float* sA  = smem;                          // 128 x 132
    float* sW1 = smem + 128 * GA_STRIDE;        // 128 x 136
    float* sW2 = sW1 + 128 * GW_STRIDE;         // 128 x 136
    float* sB1 = sW2 + 128 * GW_STRIDE;         // 128
    float* sB2 = sB1 + 128;                     // 128

    const int tid  = threadIdx.x;
    const int w    = tid >> 5;
    const int lane = tid & 31;
    const int gid  = lane >> 2;
    const int tid4 = lane & 3;
    const int m0   = blockIdx.x * 128;
    const int e0w  = (w >> 2) * 32;
    const int f0w  = (w & 3) * 32;

    for (int i = tid; i < 128 * 32; i += GT) {
        int m = i >> 5, q = (i & 31) * 4;
        float4 v = make_float4(0.f, 0.f, 0.f, 0.f);
        if (m0 + m < M) v = *(const float4*)&A[(size_t)(m0 + m) * 128 + q];
        v.x = f2tf(v.x); v.y = f2tf(v.y); v.z = f2tf(v.z); v.w = f2tf(v.w);
        *(float4*)&sA[m * GA_STRIDE + q] = v;
    }
    for (int i = tid; i < 128 * 32; i += GT) {
        int k = i >> 5, q = (i & 31) * 4;
        float4 v1 = *(const float4*)&W1[(size_t)k * 128 + q];
        v1.x = f2tf(v1.x); v1.y = f2tf(v1.y); v1.z = f2tf(v1.z); v1.w = f2tf(v1.w);
        *(float4*)&sW1[k * GW_STRIDE + q] = v1;
        float4 v2 = *(const float4*)&W2[(size_t)k * 128 + q];
        v2.x = f2tf(v2.x); v2.y = f2tf(v2.y); v2.z = f2tf(v2.z); v2.w = f2tf(v2.w);
        *(float4*)&sW2[k * GW_STRIDE + q] = v2;
    }
    for (int i = tid; i < 128; i += GT) { sB1[i] = b1[i]; sB2[i] = b2[i]; }
    __syncthreads();

    float acc[2][4][4];
    const unsigned* pA  = (const unsigned*)sA;
    const unsigned* pW1 = (const unsigned*)sW1;
    const unsigned* pW2 = (const unsigned*)sW2;

    // ---- phase 1: P1 = A @ W1 ----
    #pragma unroll
    for (int mi = 0; mi < 2; mi++)
        #pragma unroll
        for (int ni = 0; ni < 4; ni++)
            #pragma unroll
            for (int q = 0; q < 4; q++) acc[mi][ni][q] = 0.0f;
    for (int kit = 0; kit < 16; kit++) {
        int kb = kit * 8;
        unsigned a[2][4];
        #pragma unroll
        for (int mi = 0; mi < 2; mi++) {
            int rb = e0w + mi * 16;
            a[mi][0] = pA[(rb + gid)     * GA_STRIDE + kb + tid4];
            a[mi][1] = pA[(rb + gid + 8) * GA_STRIDE + kb + tid4];
            a[mi][2] = pA[(rb + gid)     * GA_STRIDE + kb + tid4 + 4];
            a[mi][3] = pA[(rb + gid + 8) * GA_STRIDE + kb + tid4 + 4];
        }
        #pragma unroll
        for (int ni = 0; ni < 4; ni++) {
            int cb = f0w + ni * 8;
            unsigned bb0 = pW1[(kb + tid4)     * GW_STRIDE + cb + gid];
            unsigned bb1 = pW1[(kb + tid4 + 4) * GW_STRIDE + cb + gid];
            mma_tf32(acc[0][ni][0], acc[0][ni][1], acc[0][ni][2], acc[0][ni][3],
                     a[0][0], a[0][1], a[0][2], a[0][3], bb0, bb1);
            mma_tf32(acc[1][ni][0], acc[1][ni][1], acc[1][ni][2], acc[1][ni][3],
                     a[1][0], a[1][1], a[1][2], a[1][3], bb0, bb1);
        }
    }
    __syncthreads();   // all warps done reading sA before overwrite with t

    // ---- epilogue 1: t = tf32(ssp(P1 + b1)) -> sA ----
    #pragma unroll
    for (int mi = 0; mi < 2; mi++) {
        int r0 = e0w + mi * 16 + gid, r1 = r0 + 8;
        #pragma unroll
        for (int ni = 0; ni < 4; ni++) {
            int cb = f0w + ni * 8 + 2 * tid4;
            float vb0 = sB1[cb], vb1 = sB1[cb + 1];
            float2 v0, v1;
            v0.x = f2tf(sspf(acc[mi][ni][0] + vb0));
            v0.y = f2tf(sspf(acc[mi][ni][1] + vb1));
            v1.x = f2tf(sspf(acc[mi][ni][2] + vb0));
            v1.y = f2tf(sspf(acc[mi][ni][3] + vb1));
            *(float2*)&sA[r0 * GA_STRIDE + cb] = v0;
            *(float2*)&sA[r1 * GA_STRIDE + cb] = v1;
        }
    }
    __syncthreads();

    // ---- phase 2: P2 = t @ W2 ----
    #pragma unroll
    for (int mi = 0; mi < 2; mi++)
        #pragma unroll
        for (int ni = 0; ni < 4; ni++)
            #pragma unroll
            for (int q = 0; q < 4; q++) acc[mi][ni][q] = 0.0f;
    for (int kit = 0; kit < 16; kit++) {
        int kb = kit * 8;
        unsigned a[2][4];
        #pragma unroll
        for (int mi = 0; mi < 2; mi++) {
            int rb = e0w + mi * 16;
            a[mi][0] = pA[(rb + gid)     * GA_STRIDE + kb + tid4];
            a[mi][1] = pA[(rb + gid + 8) * GA_STRIDE + kb + tid4];
            a[mi][2] = pA[(rb + gid)     * GA_STRIDE + kb + tid4 + 4];
            a[mi][3] = pA[(rb + gid + 8) * GA_STRIDE + kb + tid4 + 4];
        }
        #pragma unroll
        for (int ni = 0; ni < 4; ni++) {
            int cb = f0w + ni * 8;
            unsigned bb0 = pW2[(kb + tid4)     * GW_STRIDE + cb + gid];
            unsigned bb1 = pW2[(kb + tid4 + 4) * GW_STRIDE + cb + gid];
            mma_tf32(acc[0][ni][0], acc[0][ni][1], acc[0][ni][2], acc[0][ni][3],
                     a[0][0], a[0][1], a[0][2], a[0][3], bb0, bb1);
            mma_tf32(acc[1][ni][0], acc[1][ni][1], acc[1][ni][2], acc[1][ni][3],
                     a[1][0], a[1][1], a[1][2], a[1][3], bb0, bb1);
        }
    }

    // ---- epilogue 2: out = P2 + b2 (+ res) ----
    #pragma unroll
    for (int mi = 0; mi < 2; mi++) {
        int r0 = e0w + mi * 16 + gid, r1 = r0 + 8;
        int gm0 = m0 + r0, gm1 = m0 + r1;
        #pragma unroll
        for (int ni = 0; ni < 4; ni++) {
            int cb = f0w + ni * 8 + 2 * tid4;
            float vb0 = sB2[cb], vb1 = sB2[cb + 1];
            if (gm0 < M) {
                float o0 = acc[mi][ni][0] + vb0;
                float o1 = acc[mi][ni][1] + vb1;
                if (RES2) { o0 += res[(size_t)gm0 * 128 + cb]; o1 += res[(size_t)gm0 * 128 + cb + 1]; }
                *(float2*)&out[(size_t)gm0 * 128 + cb] = make_float2(o0, o1);
            }
            if (gm1 < M) {
                float o2 = acc[mi][ni][2] + vb0;
                float o3 = acc[mi][ni][3] + vb1;
                if (RES2) { o2 += res[(size_t)gm1 * 128 + cb]; o3 += res[(size_t)gm1 * 128 + cb + 1]; }
                *(float2*)&out[(size_t)gm1 * 128 + cb] = make_float2(o2, o3);
            }
        }
    }
}

// ---------------- fused edge kernel (tensor-core MLP, 512 threads) ----------
#define SW1_OFF 0
#define SW2_OFF 7616
#define SB1_OFF 25024
#define SB2_OFF 25152
#define SG_OFF  25280
#define ST_OFF  32960
#define EDGE_SMEM_FLOATS 49856
#define ETHREADS 512

__global__ __launch_bounds__(ETHREADS, 1) void edge_kernel(
        const float* __restrict__ w1, const float* __restrict__ b1,
        const float* __restrict__ w2, const float* __restrict__ b2,
        const int* __restrict__ erow, const int* __restrict__ ecol,
        const float* __restrict__ xf, float* __restrict__ agg)
{
    extern __shared__ float sm[];
    float* s_w1 = sm + SW1_OFF;
    float* s_w2 = sm + SW2_OFF;
    float* s_b1 = sm + SB1_OFF;
    float* s_b2 = sm + SB2_OFF;
    float* s_g  = sm + SG_OFF;
    float* s_t  = sm + ST_OFF;

    const int tid  = threadIdx.x;
    const int w    = tid >> 5;
    const int lane = tid & 31;
    const int gid  = lane >> 2;       // 0..7
    const int tid4 = lane & 3;        // 0..3
    const int e0w  = (w >> 2) * 32;   // 16 warps: 4 row-blocks of 32 e
    const int f0w  = (w & 3) * 32;    //           4 col-blocks of 32 f

    // ---- one-time init: weights (tf32) + biases into smem ----
    for (int i = tid; i < GG * NFF; i += ETHREADS) {
        int g = i >> 7, f = i & 127;
        s_w1[g * 136 + f] = f2tf(w1[i]);
    }
    for (int i = tid; i < 6 * 136; i += ETHREADS) s_w1[GG * 136 + i] = 0.0f;
    for (int i = tid; i < NFF * NFF; i += ETHREADS) {
        int k = i >> 7, f = i & 127;
        s_w2[k * 136 + f] = f2tf(w2[i]);
    }
    for (int i = tid; i < 128; i += ETHREADS) { s_b1[i] = b1[i]; s_b2[i] = b2[i]; }

    // scatter-phase per-thread constants: 8 edges x 4 features per thread (R13 mapping)
    const int eg = tid & 15, fg = tid >> 4;   // fg 0..31
    const int e0s = eg * 8, f0s = fg * 4;
    float b2f[4];
    __syncthreads();
    #pragma unroll
    for (int j = 0; j < 4; j++) b2f[j] = s_b2[f0s + j];

    const int ntiles = (EE + TEE - 1) / TEE;
    for (int t = blockIdx.x; t < ntiles; t += gridDim.x) {
        int base = t * TEE;

        // ---- stage A: Gaussian smearing -> s_g[e][g] (tf32), cols >=50 zero ----
        for (int i = tid; i < 56 * TEE; i += ETHREADS) {
            int e = i & 127, g = i >> 7;
            float v = 0.0f;
            if (g < GG) {
                int ge = base + e;
                float d = (ge < EE) ? g_d[ge] : 1.0e9f;  // exp -> 0 for pad
                float dd = d - (float)g * (10.0f / 49.0f);
                v = f2tf(__expf(-12.005f * dd * dd));
            }
            s_g[e * 60 + g] = v;
        }
        __syncthreads();

        // ---- stage B (mma): P = gauss @ w1 ; t1 = ssp(P + b1) -> s_t[e][f] tf32 ----
        {
            float acc[2][4][4];
            #pragma unroll
            for (int mi = 0; mi < 2; mi++)
                #pragma unroll
                for (int ni = 0; ni < 4; ni++)
                    #pragma unroll
                    for (int q = 0; q < 4; q++) acc[mi][ni][q] = 0.0f;

            const unsigned* pG  = (const unsigned*)s_g;
            const unsigned* pW1 = (const unsigned*)s_w1;
            for (int kit = 0; kit < 7; kit++) {
                int kb = kit * 8;
                unsigned a[2][4];
                #pragma unroll
                for (int mi = 0; mi < 2; mi++) {
                    int rb = e0w + mi * 16;
                    a[mi][0] = pG[(rb + gid)     * 60 + kb + tid4];
                    a[mi][1] = pG[(rb + gid + 8) * 60 + kb + tid4];
                    a[mi][2] = pG[(rb + gid)     * 60 + kb + tid4 + 4];
                    a[mi][3] = pG[(rb + gid + 8) * 60 + kb + tid4 + 4];
                }
                #pragma unroll
                for (int ni = 0; ni < 4; ni++) {
                    int cb = f0w + ni * 8;
                    unsigned bb0 = pW1[(kb + tid4)     * 136 + cb + gid];
                    unsigned bb1 = pW1[(kb + tid4 + 4) * 136 + cb + gid];
                    mma_tf32(acc[0][ni][0], acc[0][ni][1], acc[0][ni][2], acc[0][ni][3],
                             a[0][0], a[0][1], a[0][2], a[0][3], bb0, bb1);
                    mma_tf32(acc[1][ni][0], acc[1][ni][1], acc[1][ni][2], acc[1][ni][3],
                             a[1][0], a[1][1], a[1][2], a[1][3], bb0, bb1);
                }
            }
            // epilogue: ssp + bias, tf32, write s_t[e][f]
            #pragma unroll
            for (int mi = 0; mi < 2; mi++) {
                int r0 = e0w + mi * 16 + gid, r1 = r0 + 8;
                #pragma unroll
                for (int ni = 0; ni < 4; ni++) {
                    int cb = f0w + ni * 8 + 2 * tid4;
                    float vb0 = s_b1[cb], vb1 = s_b1[cb + 1];
                    float2 v0, v1;
                    v0.x = f2tf(sspf(acc[mi][ni][0] + vb0));
                    v0.y = f2tf(sspf(acc[mi][ni][1] + vb1));
                    v1.x = f2tf(sspf(acc[mi][ni][2] + vb0));
                    v1.y = f2tf(sspf(acc[mi][ni][3] + vb1));
                    *(float2*)&s_t[r0 * 132 + cb] = v0;
                    *(float2*)&s_t[r1 * 132 + cb] = v1;
                }
            }
        }
        __syncthreads();

        // ---- stage C (mma): P = t1 @ w2 ----
        {
            float acc[2][4][4];
            #pragma unroll
            for (int mi = 0; mi < 2; mi++)
                #pragma unroll
                for (int ni = 0; ni < 4; ni++)
                    #pragma unroll
                    for (int q = 0; q < 4; q++) acc[mi][ni][q] = 0.0f;

            const unsigned* pT  = (const unsigned*)s_t;
            const unsigned* pW2 = (const unsigned*)s_w2;
            for (int kit = 0; kit < 16; kit++) {
                int kb = kit * 8;
                unsigned a[2][4];
                #pragma unroll
                for (int mi = 0; mi < 2; mi++) {
                    int rb = e0w + mi * 16;
                    a[mi][0] = pT[(rb + gid)     * 132 + kb + tid4];
                    a[mi][1] = pT[(rb + gid + 8) * 132 + kb + tid4];
                    a[mi][2] = pT[(rb + gid)     * 132 + kb + tid4 + 4];
                    a[mi][3] = pT[(rb + gid + 8) * 132 + kb + tid4 + 4];
                }
                #pragma unroll
                for (int ni = 0; ni < 4; ni++) {
                    int cb = f0w + ni * 8;
                    unsigned bb0 = pW2[(kb + tid4)     * 136 + cb + gid];
                    unsigned bb1 = pW2[(kb + tid4 + 4) * 136 + cb + gid];
                    mma_tf32(acc[0][ni][0], acc[0][ni][1], acc[0][ni][2], acc[0][ni][3],
                             a[0][0], a[0][1], a[0][2], a[0][3], bb0, bb1);
                    mma_tf32(acc[1][ni][0], acc[1][ni][1], acc[1][ni][2], acc[1][ni][3],
                             a[1][0], a[1][1], a[1][2], a[1][3], bb0, bb1);
                }
            }
            __syncthreads();   // all warps done reading s_t before overwriting it with P
            #pragma unroll
            for (int mi = 0; mi < 2; mi++) {
                int r0 = e0w + mi * 16 + gid, r1 = r0 + 8;
                #pragma unroll
                for (int ni = 0; ni < 4; ni++) {
                    int cb = f0w + ni * 8 + 2 * tid4;
                    *(float2*)&s_t[r0 * 132 + cb] = make_float2(acc[mi][ni][0], acc[mi][ni][1]);
                    *(float2*)&s_t[r1 * 132 + cb] = make_float2(acc[mi][ni][2], acc[mi][ni][3]);
                }
            }
        }
        __syncthreads();

        // ---- scatter (R13 mapping): 8 edges x 4 features per thread ----
        #pragma unroll
        for (int ei = 0; ei < 8; ei++) {
            int e = base + e0s + ei;
            if (e < EE) {
                int r = erow[e], c = ecol[e];
                float Ce = g_Cc[e];
                float4 xv = *(const float4*)&xf[r * 128 + f0s];
                float4 p  = *(const float4*)&s_t[(e0s + ei) * 132 + f0s];
                float m0 = (p.x + b2f[0]) * Ce * xv.x;
                float m1 = (p.y + b2f[1]) * Ce * xv.y;
                float m2 = (p.z + b2f[2]) * Ce * xv.z;
                float m3 = (p.w + b2f[3]) * Ce * xv.w;
                red_v4(&agg[c * 128 + f0s], m0, m1, m2, m3);
            }
        }
        // scatter precedes next stage A; post-A __syncthreads orders the s_t
        // readers here against the next tile's stage-B writers.
    }
}

// ---------------- pooling ---------------------------------------------------
__global__ void pool1_kernel(const int* __restrict__ a2c, const float* __restrict__ h2) {
    int idx = blockIdx.x * blockDim.x + threadIdx.x;  // over NN*32 quads
    if (idx < NN * 32) {
        int n = idx >> 5, q = (idx & 31) * 4;
        float4 v = *(const float4*)&h2[n * 128 + q];
        red_v4(&g_conf[a2c[n] * 128 + q], v.x, v.y, v.z, v.w);
    }
}
__global__ void pool2_kernel(const int* __restrict__ c2m) {
    int idx = blockIdx.x * blockDim.x + threadIdx.x;  // over NCC*32 quads
    if (idx < NCC * 32) {
        int n = idx >> 5, q = (idx & 31) * 4;
        float4 v = *(const float4*)&g_conf[n * 128 + q];
        red_v4(&g_mol[c2m[n] * 128 + q], v.x, v.y, v.z, v.w);
    }
}

// ---------------- head ------------------------------------------------------
__global__ void head_kernel(const float* __restrict__ w1, const float* __restrict__ b1_,
                            const float* __restrict__ w2, const float* __restrict__ b2_,
                            float* __restrict__ out) {
    __shared__ float red[2];
    int m = blockIdx.x, f = threadIdx.x;  // 64 threads
    float s = b1_[f];
    #pragma unroll 4
    for (int k = 0; k < 128; k++)
        s = fmaf(g_mol[m * 128 + k], w1[k * 64 + f], s);
    float v = sspf(s) * w2[f];
    #pragma unroll
    for (int o = 16; o; o >>= 1) v += __shfl_xor_sync(0xffffffffu, v, o);
    if ((f & 31) == 0) red[f >> 5] = v;
    __syncthreads();
    if (f == 0) out[m] = red[0] + red[1] + b2_[0];
}

// ---------------- launch ----------------------------------------------------
extern "C" void kernel_launch(void* const* d_in, const int* in_sizes, int n_in,
                              void* d_out, int out_size) {
    const int*   z    = (const int*)  d_in[0];
    const float* pos  = (const float*)d_in[1];
    const int*   erow = (const int*)  d_in[2];
    const int*   ecol = (const int*)  d_in[3];
    const int*   a2c  = (const int*)  d_in[4];
    const int*   c2m  = (const int*)  d_in[5];
    const float* emb  = (const float*)d_in[6];
    const float* mw1  = (const float*)d_in[7];
    const float* mb1  = (const float*)d_in[8];
    const float* mw2  = (const float*)d_in[9];
    const float* mb2  = (const float*)d_in[10];
    const float* cl1  = (const float*)d_in[11];
    const float* cl2  = (const float*)d_in[12];
    const float* cl2b = (const float*)d_in[13];
    const float* ilw  = (const float*)d_in[14];
    const float* ilb  = (const float*)d_in[15];
    const float* l1w  = (const float*)d_in[16];
    const float* l1b  = (const float*)d_in[17];
    const float* l2w  = (const float*)d_in[18];
    const float* l2b  = (const float*)d_in[19];
    const float* hw1  = (const float*)d_in[20];
    const float* hb1  = (const float*)d_in[21];
    const float* hw2  = (const float*)d_in[22];
    const float* hb2  = (const float*)d_in[23];
    float* out = (float*)d_out;

    const int EDGE_SMEM = EDGE_SMEM_FLOATS * 4;  // 199424 B
    cudaFuncSetAttribute(edge_kernel, cudaFuncAttributeMaxDynamicSharedMemorySize, EDGE_SMEM);
    cudaFuncSetAttribute(gemm_tc, cudaFuncAttributeMaxDynamicSharedMemorySize, GEMM_TC_SMEM);
    cudaFuncSetAttribute(gemm2_tc<true>,  cudaFuncAttributeMaxDynamicSharedMemorySize, GEMM2_SMEM);
    cudaFuncSetAttribute(gemm2_tc<false>, cudaFuncAttributeMaxDynamicSharedMemorySize, GEMM2_SMEM);

    float *ph, *pxf, *pagg, *pconf, *pmol;
    cudaGetSymbolAddress((void**)&ph,   g_h);
    cudaGetSymbolAddress((void**)&pxf,  g_xf);
    cudaGetSymbolAddress((void**)&pagg, g_agg);
    cudaGetSymbolAddress((void**)&pconf, g_conf);
    cudaGetSymbolAddress((void**)&pmol,  g_mol);

    const int GEMM_BLOCKS = (NN + 127) / 128;  // 391

    embed_kernel<<<(NN * HH + 255) / 256, 256>>>(z, emb);
    geom_kernel<<<(EE + 255) / 256, 256>>>(pos, erow, ecol);

    for (int i = 0; i < LL; i++) {
        gemm_tc<<<GEMM_BLOCKS, GT, GEMM_TC_SMEM>>>(ph, cl1 + (size_t)i * HH * NFF, pxf, NN);
        cudaMemsetAsync(pagg, 0, (size_t)NN * HH * sizeof(float));
        edge_kernel<<<152, ETHREADS, EDGE_SMEM>>>(mw1 + (size_t)i * GG * NFF,
                                                  mb1 + (size_t)i * NFF,
                                                  mw2 + (size_t)i * NFF * NFF,
                                                  mb2 + (size_t)i * NFF,
                                                  erow, ecol, pxf, pagg);
        // fused: x = agg@cl2 + b ; h = h + ssp(x)@ilw + b
        gemm2_tc<true><<<GEMM_BLOCKS, GT, GEMM2_SMEM>>>(pagg,
                                                        cl2 + (size_t)i * NFF * HH,
                                                        cl2b + (size_t)i * HH,
                                                        ilw + (size_t)i * HH * HH,
                                                        ilb + (size_t)i * HH,
                                                        ph, ph, NN);
    }

    // final fused: h2 = ssp(h@lin1 + b)@lin2 + b -> g_xf
    gemm2_tc<false><<<GEMM_BLOCKS, GT, GEMM2_SMEM>>>(ph, l1w, l1b, l2w, l2b,
                                                     nullptr, pxf, NN);

    cudaMemsetAsync(pconf, 0, (size_t)NCC * HH * sizeof(float));
    cudaMemsetAsync(pmol,  0, (size_t)NMM * HH * sizeof(float));
    pool1_kernel<<<(NN * 32 + 255) / 256, 256>>>(a2c, pxf);
    pool2_kernel<<<(NCC * 32 + 255) / 256, 256>>>(c2m);
    head_kernel<<<NMM, 64>>>(hw1, hb1, hw2, hb2, out);
}

// round 17
// speedup vs baseline: 1.3079x; 1.1202x over previous
#include <cuda_runtime.h>
#include <cuda_fp16.h>
#include <math.h>

#define NN   50000
#define EE   600000
#define HH   128
#define GG   50
#define NFF  128
#define LL   6
#define NCC  500
#define NMM  100
#define TEE  128   // edges per tile in edge kernel

// ---------------- scratch (device globals; no allocation allowed) ----------
__device__ float g_h[NN*HH];
__device__ float g_xf[NN*HH];
__device__ float g_agg[NN*HH];
__device__ float g_d[EE];
__device__ float g_Cc[EE];
__device__ float g_conf[NCC*HH];
__device__ float g_mol[NMM*HH];

__device__ __forceinline__ float sspf(float x) {
    // shifted softplus: log(1+exp(x)) - log(2); t in (0,1] so __logf(1+t) is accurate
    float t = __expf(-fabsf(x));
    return fmaxf(x, 0.0f) + __logf(1.0f + t) - 0.69314718055994531f;
}

// 4-wide global reduction (sm_90+)
__device__ __forceinline__ void red_v4(float* addr, float a, float b, float c, float d) {
    asm volatile("red.global.add.v4.f32 [%0], {%1, %2, %3, %4};"
                 :: "l"(addr), "f"(a), "f"(b), "f"(c), "f"(d) : "memory");
}

// tf32 helpers
__device__ __forceinline__ float f2tf(float x) {
    unsigned r;
    asm("cvt.rna.tf32.f32 %0, %1;" : "=r"(r) : "f"(x));
    return __uint_as_float(r);
}
__device__ __forceinline__ void mma_tf32(float& c0, float& c1, float& c2, float& c3,
                                         unsigned a0, unsigned a1, unsigned a2, unsigned a3,
                                         unsigned b0, unsigned b1) {
    asm("mma.sync.aligned.m16n8k8.row.col.f32.tf32.tf32.f32 "
        "{%0,%1,%2,%3}, {%4,%5,%6,%7}, {%8,%9}, {%0,%1,%2,%3};"
        : "+f"(c0), "+f"(c1), "+f"(c2), "+f"(c3)
        : "r"(a0), "r"(a1), "r"(a2), "r"(a3), "r"(b0), "r"(b1));
}
// fp16 mma m16n8k16 (10-bit mantissa == tf32 precision)
__device__ __forceinline__ void mma_f16(float& c0, float& c1, float& c2, float& c3,
                                        unsigned a0, unsigned a1, unsigned a2, unsigned a3,
                                        unsigned b0, unsigned b1) {
    asm("mma.sync.aligned.m16n8k16.row.col.f32.f16.f16.f32 "
        "{%0,%1,%2,%3}, {%4,%5,%6,%7}, {%8,%9}, {%0,%1,%2,%3};"
        : "+f"(c0), "+f"(c1), "+f"(c2), "+f"(c3)
        : "r"(a0), "r"(a1), "r"(a2), "r"(a3), "r"(b0), "r"(b1));
}

// ---------------- embedding -------------------------------------------------
__global__ void embed_kernel(const int* __restrict__ z, const float* __restrict__ emb) {
    int idx = blockIdx.x * blockDim.x + threadIdx.x;
    if (idx < NN * HH) {
        g_h[idx] = emb[z[idx >> 7] * HH + (idx & 127)];
    }
}

// ---------------- edge geometry --------------------------------------------
__global__ void geom_kernel(const float* __restrict__ pos,
                            const int* __restrict__ er, const int* __restrict__ ec) {
    int e = blockIdx.x * blockDim.x + threadIdx.x;
    if (e < EE) {
        int r = er[e], c = ec[e];
        float dx = pos[3*r+0] - pos[3*c+0];
        float dy = pos[3*r+1] - pos[3*c+1];
        float dz = pos[3*r+2] - pos[3*c+2];
        float d = sqrtf(dx*dx + dy*dy + dz*dz);
        g_d[e]  = d;
        g_Cc[e] = 0.5f * (cosf(d * 0.31415926535897931f) + 1.0f);
    }
}

// ---------------- tensor-core node GEMM (tf32 mma) --------------------------
#define GT 512
#define GA_STRIDE 132
#define GW_STRIDE 136
#define GEMM_TC_SMEM ((128*GA_STRIDE + 128*GW_STRIDE + 128) * 4)

__global__ __launch_bounds__(GT, 1) void gemm_tc(
        const float* __restrict__ A, const float* __restrict__ W,
        float* __restrict__ out, int M)
{
    extern __shared__ float smem[];
    float* sA = smem;                       // 128 x 132
    float* sW = smem + 128 * GA_STRIDE;     // 128 x 136

    const int tid  = threadIdx.x;
    const int w    = tid >> 5;
    const int lane = tid & 31;
    const int gid  = lane >> 2;
    const int tid4 = lane & 3;
    const int m0   = blockIdx.x * 128;
    const int e0w  = (w >> 2) * 32;
    const int f0w  = (w & 3) * 32;

    for (int i = tid; i < 128 * 32; i += GT) {
        int m = i >> 5, q = (i & 31) * 4;
        float4 v = make_float4(0.f, 0.f, 0.f, 0.f);
        if (m0 + m < M) v = *(const float4*)&A[(size_t)(m0 + m) * 128 + q];
        v.x = f2tf(v.x); v.y = f2tf(v.y); v.z = f2tf(v.z); v.w = f2tf(v.w);
        *(float4*)&sA[m * GA_STRIDE + q] = v;
    }
    for (int i = tid; i < 128 * 32; i += GT) {
        int k = i >> 5, q = (i & 31) * 4;
        float4 v = *(const float4*)&W[(size_t)k * 128 + q];
        v.x = f2tf(v.x); v.y = f2tf(v.y); v.z = f2tf(v.z); v.w = f2tf(v.w);
        *(float4*)&sW[k * GW_STRIDE + q] = v;
    }
    __syncthreads();

    float acc[2][4][4];
    #pragma unroll
    for (int mi = 0; mi < 2; mi++)
        #pragma unroll
        for (int ni = 0; ni < 4; ni++)
            #pragma unroll
            for (int q = 0; q < 4; q++) acc[mi][ni][q] = 0.0f;

    const unsigned* pA = (const unsigned*)sA;
    const unsigned* pW = (const unsigned*)sW;
    for (int kit = 0; kit < 16; kit++) {
        int kb = kit * 8;
        unsigned a[2][4];
        #pragma unroll
        for (int mi = 0; mi < 2; mi++) {
            int rb = e0w + mi * 16;
            a[mi][0] = pA[(rb + gid)     * GA_STRIDE + kb + tid4];
            a[mi][1] = pA[(rb + gid + 8) * GA_STRIDE + kb + tid4];
            a[mi][2] = pA[(rb + gid)     * GA_STRIDE + kb + tid4 + 4];
            a[mi][3] = pA[(rb + gid + 8) * GA_STRIDE + kb + tid4 + 4];
        }
        #pragma unroll
        for (int ni = 0; ni < 4; ni++) {
            int cb = f0w + ni * 8;
            unsigned bb0 = pW[(kb + tid4)     * GW_STRIDE + cb + gid];
            unsigned bb1 = pW[(kb + tid4 + 4) * GW_STRIDE + cb + gid];
            mma_tf32(acc[0][ni][0], acc[0][ni][1], acc[0][ni][2], acc[0][ni][3],
                     a[0][0], a[0][1], a[0][2], a[0][3], bb0, bb1);
            mma_tf32(acc[1][ni][0], acc[1][ni][1], acc[1][ni][2], acc[1][ni][3],
                     a[1][0], a[1][1], a[1][2], a[1][3], bb0, bb1);
        }
    }

    #pragma unroll
    for (int mi = 0; mi < 2; mi++) {
        int r0 = e0w + mi * 16 + gid, r1 = r0 + 8;
        int gm0 = m0 + r0, gm1 = m0 + r1;
        #pragma unroll
        for (int ni = 0; ni < 4; ni++) {
            int cb = f0w + ni * 8 + 2 * tid4;
            if (gm0 < M)
                *(float2*)&out[(size_t)gm0 * 128 + cb] = make_float2(acc[mi][ni][0], acc[mi][ni][1]);
            if (gm1 < M)
                *(float2*)&out[(size_t)gm1 * 128 + cb] = make_float2(acc[mi][ni][2], acc[mi][ni][3]);
        }
    }
}

// ---------------- fused double GEMM (tf32 mma) -------------------------------
#define GEMM2_SMEM ((128*GA_STRIDE + 2*128*GW_STRIDE + 256) * 4)

template<bool RES2>
__global__ __launch_bounds__(GT, 1) void gemm2_tc(
        const float* __restrict__ A,
        const float* __restrict__ W1, const float* __restrict__ b1,
        const float* __restrict__ W2, const float* __restrict__ b2,
        const float* __restrict__ res, float* __restrict__ out, int M)
{
    extern __shared__ float smem[];
    float* sA  = smem;                          // 128 x 132
    float* sW1 = smem + 128 * GA_STRIDE;        // 128 x 136
    float* sW2 = sW1 + 128 * GW_STRIDE;         // 128 x 136
    float* sB1 = sW2 + 128 * GW_STRIDE;         // 128
    float* sB2 = sB1 + 128;                     // 128

    const int tid  = threadIdx.x;
    const int w    = tid >> 5;
    const int lane = tid & 31;
    const int gid  = lane >> 2;
    const int tid4 = lane & 3;
    const int m0   = blockIdx.x * 128;
    const int e0w  = (w >> 2) * 32;
    const int f0w  = (w & 3) * 32;

    for (int i = tid; i < 128 * 32; i += GT) {
        int m = i >> 5, q = (i & 31) * 4;
        float4 v = make_float4(0.f, 0.f, 0.f, 0.f);
        if (m0 + m < M) v = *(const float4*)&A[(size_t)(m0 + m) * 128 + q];
        v.x = f2tf(v.x); v.y = f2tf(v.y); v.z = f2tf(v.z); v.w = f2tf(v.w);
        *(float4*)&sA[m * GA_STRIDE + q] = v;
    }
    for (int i = tid; i < 128 * 32; i += GT) {
        int k = i >> 5, q = (i & 31) * 4;
        float4 v1 = *(const float4*)&W1[(size_t)k * 128 + q];
        v1.x = f2tf(v1.x); v1.y = f2tf(v1.y); v1.z = f2tf(v1.z); v1.w = f2tf(v1.w);
        *(float4*)&sW1[k * GW_STRIDE + q] = v1;
        float4 v2 = *(const float4*)&W2[(size_t)k * 128 + q];
        v2.x = f2tf(v2.x); v2.y = f2tf(v2.y); v2.z = f2tf(v2.z); v2.w = f2tf(v2.w);
        *(float4*)&sW2[k * GW_STRIDE + q] = v2;
    }
    for (int i = tid; i < 128; i += GT) { sB1[i] = b1[i]; sB2[i] = b2[i]; }
    __syncthreads();

    float acc[2][4][4];
    const unsigned* pA  = (const unsigned*)sA;
    const unsigned* pW1 = (const unsigned*)sW1;
    const unsigned* pW2 = (const unsigned*)sW2;

    // ---- phase 1: P1 = A @ W1 ----
    #pragma unroll
    for (int mi = 0; mi < 2; mi++)
        #pragma unroll
        for (int ni = 0; ni < 4; ni++)
            #pragma unroll
            for (int q = 0; q < 4; q++) acc[mi][ni][q] = 0.0f;
    for (int kit = 0; kit < 16; kit++) {
        int kb = kit * 8;
        unsigned a[2][4];
        #pragma unroll
        for (int mi = 0; mi < 2; mi++) {
            int rb = e0w + mi * 16;
            a[mi][0] = pA[(rb + gid)     * GA_STRIDE + kb + tid4];
            a[mi][1] = pA[(rb + gid + 8) * GA_STRIDE + kb + tid4];
            a[mi][2] = pA[(rb + gid)     * GA_STRIDE + kb + tid4 + 4];
            a[mi][3] = pA[(rb + gid + 8) * GA_STRIDE + kb + tid4 + 4];
        }
        #pragma unroll
        for (int ni = 0; ni < 4; ni++) {
            int cb = f0w + ni * 8;
            unsigned bb0 = pW1[(kb + tid4)     * GW_STRIDE + cb + gid];
            unsigned bb1 = pW1[(kb + tid4 + 4) * GW_STRIDE + cb + gid];
            mma_tf32(acc[0][ni][0], acc[0][ni][1], acc[0][ni][2], acc[0][ni][3],
                     a[0][0], a[0][1], a[0][2], a[0][3], bb0, bb1);
            mma_tf32(acc[1][ni][0], acc[1][ni][1], acc[1][ni][2], acc[1][ni][3],
                     a[1][0], a[1][1], a[1][2], a[1][3], bb0, bb1);
        }
    }
    __syncthreads();   // all warps done reading sA before overwrite with t

    // ---- epilogue 1: t = tf32(ssp(P1 + b1)) -> sA ----
    #pragma unroll
    for (int mi = 0; mi < 2; mi++) {
        int r0 = e0w + mi * 16 + gid, r1 = r0 + 8;
        #pragma unroll
        for (int ni = 0; ni < 4; ni++) {
            int cb = f0w + ni * 8 + 2 * tid4;
            float vb0 = sB1[cb], vb1 = sB1[cb + 1];
            float2 v0, v1;
            v0.x = f2tf(sspf(acc[mi][ni][0] + vb0));
            v0.y = f2tf(sspf(acc[mi][ni][1] + vb1));
            v1.x = f2tf(sspf(acc[mi][ni][2] + vb0));
            v1.y = f2tf(sspf(acc[mi][ni][3] + vb1));
            *(float2*)&sA[r0 * GA_STRIDE + cb] = v0;
            *(float2*)&sA[r1 * GA_STRIDE + cb] = v1;
        }
    }
    __syncthreads();

    // ---- phase 2: P2 = t @ W2 ----
    #pragma unroll
    for (int mi = 0; mi < 2; mi++)
        #pragma unroll
        for (int ni = 0; ni < 4; ni++)
            #pragma unroll
            for (int q = 0; q < 4; q++) acc[mi][ni][q] = 0.0f;
    for (int kit = 0; kit < 16; kit++) {
        int kb = kit * 8;
        unsigned a[2][4];
        #pragma unroll
        for (int mi = 0; mi < 2; mi++) {
            int rb = e0w + mi * 16;
            a[mi][0] = pA[(rb + gid)     * GA_STRIDE + kb + tid4];
            a[mi][1] = pA[(rb + gid + 8) * GA_STRIDE + kb + tid4];
            a[mi][2] = pA[(rb + gid)     * GA_STRIDE + kb + tid4 + 4];
            a[mi][3] = pA[(rb + gid + 8) * GA_STRIDE + kb + tid4 + 4];
        }
        #pragma unroll
        for (int ni = 0; ni < 4; ni++) {
            int cb = f0w + ni * 8;
            unsigned bb0 = pW2[(kb + tid4)     * GW_STRIDE + cb + gid];
            unsigned bb1 = pW2[(kb + tid4 + 4) * GW_STRIDE + cb + gid];
            mma_tf32(acc[0][ni][0], acc[0][ni][1], acc[0][ni][2], acc[0][ni][3],
                     a[0][0], a[0][1], a[0][2], a[0][3], bb0, bb1);
            mma_tf32(acc[1][ni][0], acc[1][ni][1], acc[1][ni][2], acc[1][ni][3],
                     a[1][0], a[1][1], a[1][2], a[1][3], bb0, bb1);
        }
    }

    // ---- epilogue 2: out = P2 + b2 (+ res) ----
    #pragma unroll
    for (int mi = 0; mi < 2; mi++) {
        int r0 = e0w + mi * 16 + gid, r1 = r0 + 8;
        int gm0 = m0 + r0, gm1 = m0 + r1;
        #pragma unroll
        for (int ni = 0; ni < 4; ni++) {
            int cb = f0w + ni * 8 + 2 * tid4;
            float vb0 = sB2[cb], vb1 = sB2[cb + 1];
            if (gm0 < M) {
                float o0 = acc[mi][ni][0] + vb0;
                float o1 = acc[mi][ni][1] + vb1;
                if (RES2) { o0 += res[(size_t)gm0 * 128 + cb]; o1 += res[(size_t)gm0 * 128 + cb + 1]; }
                *(float2*)&out[(size_t)gm0 * 128 + cb] = make_float2(o0, o1);
            }
            if (gm1 < M) {
                float o2 = acc[mi][ni][2] + vb0;
                float o3 = acc[mi][ni][3] + vb1;
                if (RES2) { o2 += res[(size_t)gm1 * 128 + cb]; o3 += res[(size_t)gm1 * 128 + cb + 1]; }
                *(float2*)&out[(size_t)gm1 * 128 + cb] = make_float2(o2, o3);
            }
        }
    }
}

// ---------------- fused edge kernel (tf32 stage B, fp16 stage C) ------------
// smem (float offsets):
//   s_w1  tf32 56x136        @ 0      (7616)
//   s_b1  f32 128            @ 7616
//   s_b2  f32 128            @ 7744
//   s_g   tf32 128x60 [e][g] @ 7872   (7680)
//   s_p   f32 128x132 [e][f] @ 15552  (16896)   stage-C output P
//   s_w2h f16 128x136 [n][k] @ 32448  (8704 fl) transposed, half2-packed k
//   s_th  f16 128x136 [e][k] @ 41152  (8704 fl) t1, half2-packed k
#define SW1_OFF 0
#define SB1_OFF 7616
#define SB2_OFF 7744
#define SG_OFF  7872
#define SP_OFF  15552
#define SW2H_OFF 32448
#define STH_OFF 41152
#define EDGE_SMEM_FLOATS 49856
#define ETHREADS 512

__global__ __launch_bounds__(ETHREADS, 1) void edge_kernel(
        const float* __restrict__ w1, const float* __restrict__ b1,
        const float* __restrict__ w2, const float* __restrict__ b2,
        const int* __restrict__ erow, const int* __restrict__ ecol,
        const float* __restrict__ xf, float* __restrict__ agg)
{
    extern __shared__ float sm[];
    float*  s_w1  = sm + SW1_OFF;
    float*  s_b1  = sm + SB1_OFF;
    float*  s_b2  = sm + SB2_OFF;
    float*  s_g   = sm + SG_OFF;
    float*  s_p   = sm + SP_OFF;
    __half* s_w2h = (__half*)(sm + SW2H_OFF);
    __half* s_th  = (__half*)(sm + STH_OFF);

    const int tid  = threadIdx.x;
    const int w    = tid >> 5;
    const int lane = tid & 31;
    const int gid  = lane >> 2;       // 0..7
    const int tid4 = lane & 3;        // 0..3
    const int e0w  = (w >> 2) * 32;   // 16 warps: 4 row-blocks of 32 e
    const int f0w  = (w & 3) * 32;    //           4 col-blocks of 32 f

    // ---- one-time init ----
    for (int i = tid; i < GG * NFF; i += ETHREADS) {
        int g = i >> 7, f = i & 127;
        s_w1[g * 136 + f] = f2tf(w1[i]);
    }
    for (int i = tid; i < 6 * 136; i += ETHREADS) s_w1[GG * 136 + i] = 0.0f;
    for (int i = tid; i < NFF * NFF; i += ETHREADS) {
        int k = i >> 7, f = i & 127;
        s_w2h[f * 136 + k] = __float2half(w2[i]);   // transposed [n][k]
    }
    for (int i = tid; i < 128; i += ETHREADS) { s_b1[i] = b1[i]; s_b2[i] = b2[i]; }

    // scatter constants: 8 edges x 4 features per thread (R13 mapping)
    const int eg = tid & 15, fg = tid >> 4;   // fg 0..31
    const int e0s = eg * 8, f0s = fg * 4;
    float b2f[4];
    __syncthreads();
    #pragma unroll
    for (int j = 0; j < 4; j++) b2f[j] = s_b2[f0s + j];

    const int ntiles = (EE + TEE - 1) / TEE;
    for (int t = blockIdx.x; t < ntiles; t += gridDim.x) {
        int base = t * TEE;

        // ---- stage A: Gaussian smearing -> s_g[e][g] (tf32), cols >=50 zero ----
        for (int i = tid; i < 56 * TEE; i += ETHREADS) {
            int e = i & 127, g = i >> 7;
            float v = 0.0f;
            if (g < GG) {
                int ge = base + e;
                float d = (ge < EE) ? g_d[ge] : 1.0e9f;  // exp -> 0 for pad
                float dd = d - (float)g * (10.0f / 49.0f);
                v = f2tf(__expf(-12.005f * dd * dd));
            }
            s_g[e * 60 + g] = v;
        }
        __syncthreads();

        // ---- stage B (tf32 mma): t1 = ssp(gauss @ w1 + b1) -> s_th fp16 ----
        {
            float acc[2][4][4];
            #pragma unroll
            for (int mi = 0; mi < 2; mi++)
                #pragma unroll
                for (int ni = 0; ni < 4; ni++)
                    #pragma unroll
                    for (int q = 0; q < 4; q++) acc[mi][ni][q] = 0.0f;

            const unsigned* pG  = (const unsigned*)s_g;
            const unsigned* pW1 = (const unsigned*)s_w1;
            for (int kit = 0; kit < 7; kit++) {
                int kb = kit * 8;
                unsigned a[2][4];
                #pragma unroll
                for (int mi = 0; mi < 2; mi++) {
                    int rb = e0w + mi * 16;
                    a[mi][0] = pG[(rb + gid)     * 60 + kb + tid4];
                    a[mi][1] = pG[(rb + gid + 8) * 60 + kb + tid4];
                    a[mi][2] = pG[(rb + gid)     * 60 + kb + tid4 + 4];
                    a[mi][3] = pG[(rb + gid + 8) * 60 + kb + tid4 + 4];
                }
                #pragma unroll
                for (int ni = 0; ni < 4; ni++) {
                    int cb = f0w + ni * 8;
                    unsigned bb0 = pW1[(kb + tid4)     * 136 + cb + gid];
                    unsigned bb1 = pW1[(kb + tid4 + 4) * 136 + cb + gid];
                    mma_tf32(acc[0][ni][0], acc[0][ni][1], acc[0][ni][2], acc[0][ni][3],
                             a[0][0], a[0][1], a[0][2], a[0][3], bb0, bb1);
                    mma_tf32(acc[1][ni][0], acc[1][ni][1], acc[1][ni][2], acc[1][ni][3],
                             a[1][0], a[1][1], a[1][2], a[1][3], bb0, bb1);
                }
            }
            // epilogue: ssp + bias -> half2-packed s_th[e][k-pairs]
            __half2* pTH = (__half2*)s_th;   // u32-unit stride 68
            #pragma unroll
            for (int mi = 0; mi < 2; mi++) {
                int r0 = e0w + mi * 16 + gid, r1 = r0 + 8;
                #pragma unroll
                for (int ni = 0; ni < 4; ni++) {
                    int cbase = f0w + ni * 8;
                    int c0 = cbase + 2 * tid4;
                    float vb0 = s_b1[c0], vb1 = s_b1[c0 + 1];
                    __half2 h0 = __floats2half2_rn(sspf(acc[mi][ni][0] + vb0),
                                                   sspf(acc[mi][ni][1] + vb1));
                    __half2 h1 = __floats2half2_rn(sspf(acc[mi][ni][2] + vb0),
                                                   sspf(acc[mi][ni][3] + vb1));
                    pTH[r0 * 68 + (cbase >> 1) + tid4] = h0;
                    pTH[r1 * 68 + (cbase >> 1) + tid4] = h1;
                }
            }
        }
        __syncthreads();

        // ---- stage C (fp16 mma m16n8k16): P = t1 @ w2 -> s_p (fp32) ----
        {
            float acc[2][4][4];
            #pragma unroll
            for (int mi = 0; mi < 2; mi++)
                #pragma unroll
                for (int ni = 0; ni < 4; ni++)
                    #pragma unroll
                    for (int q = 0; q < 4; q++) acc[mi][ni][q] = 0.0f;

            const unsigned* pT  = (const unsigned*)s_th;    // stride 68 u32
            const unsigned* pW2 = (const unsigned*)s_w2h;   // stride 68 u32
            for (int kit = 0; kit < 8; kit++) {
                int kh = kit * 8;   // u32 units (= 16 fp16 per kit)
                unsigned a[2][4];
                #pragma unroll
                for (int mi = 0; mi < 2; mi++) {
                    int rb = e0w + mi * 16;
                    a[mi][0] = pT[(rb + gid)     * 68 + kh + tid4];
                    a[mi][1] = pT[(rb + gid + 8) * 68 + kh + tid4];
                    a[mi][2] = pT[(rb + gid)     * 68 + kh + 4 + tid4];
                    a[mi][3] = pT[(rb + gid + 8) * 68 + kh + 4 + tid4];
                }
                #pragma unroll
                for (int ni = 0; ni < 4; ni++) {
                    int cb = f0w + ni * 8;
                    unsigned bb0 = pW2[(cb + gid) * 68 + kh + tid4];
                    unsigned bb1 = pW2[(cb + gid) * 68 + kh + 4 + tid4];
                    mma_f16(acc[0][ni][0], acc[0][ni][1], acc[0][ni][2], acc[0][ni][3],
                            a[0][0], a[0][1], a[0][2], a[0][3], bb0, bb1);
                    mma_f16(acc[1][ni][0], acc[1][ni][1], acc[1][ni][2], acc[1][ni][3],
                            a[1][0], a[1][1], a[1][2], a[1][3], bb0, bb1);
                }
            }
            // epilogue writes s_p (separate buffer, no race with C k-loop readers;
            // scatter(t-1) readers of s_p are ordered by the post-A and post-B syncs)
            #pragma unroll
            for (int mi = 0; mi < 2; mi++) {
                int r0 = e0w + mi * 16 + gid, r1 = r0 + 8;
                #pragma unroll
                for (int ni = 0; ni < 4; ni++) {
                    int cb = f0w + ni * 8 + 2 * tid4;
                    *(float2*)&s_p[r0 * 132 + cb] = make_float2(acc[mi][ni][0], acc[mi][ni][1]);
                    *(float2*)&s_p[r1 * 132 + cb] = make_float2(acc[mi][ni][2], acc[mi][ni][3]);
                }
            }
        }
        __syncthreads();

        // ---- scatter (R13 mapping): 8 edges x 4 features per thread ----
        #pragma unroll
        for (int ei = 0; ei < 8; ei++) {
            int e = base + e0s + ei;
            if (e < EE) {
                int r = erow[e], c = ecol[e];
                float Ce = g_Cc[e];
                float4 xv = *(const float4*)&xf[r * 128 + f0s];
                float4 p  = *(const float4*)&s_p[(e0s + ei) * 132 + f0s];
                float m0 = (p.x + b2f[0]) * Ce * xv.x;
                float m1 = (p.y + b2f[1]) * Ce * xv.y;
                float m2 = (p.z + b2f[2]) * Ce * xv.z;
                float m3 = (p.w + b2f[3]) * Ce * xv.w;
                red_v4(&agg[c * 128 + f0s], m0, m1, m2, m3);
            }
        }
        // scatter precedes next stage A; the post-A and post-B syncs order
        // scatter's s_p reads against the next tile's stage-C writers.
    }
}

// ---------------- pooling ---------------------------------------------------
__global__ void pool1_kernel(const int* __restrict__ a2c, const float* __restrict__ h2) {
    int idx = blockIdx.x * blockDim.x + threadIdx.x;  // over NN*32 quads
    if (idx < NN * 32) {
        int n = idx >> 5, q = (idx & 31) * 4;
        float4 v = *(const float4*)&h2[n * 128 + q];
        red_v4(&g_conf[a2c[n] * 128 + q], v.x, v.y, v.z, v.w);
    }
}
__global__ void pool2_kernel(const int* __restrict__ c2m) {
    int idx = blockIdx.x * blockDim.x + threadIdx.x;  // over NCC*32 quads
    if (idx < NCC * 32) {
        int n = idx >> 5, q = (idx & 31) * 4;
        float4 v = *(const float4*)&g_conf[n * 128 + q];
        red_v4(&g_mol[c2m[n] * 128 + q], v.x, v.y, v.z, v.w);
    }
}

// ---------------- head ------------------------------------------------------
__global__ void head_kernel(const float* __restrict__ w1, const float* __restrict__ b1_,
                            const float* __restrict__ w2, const float* __restrict__ b2_,
                            float* __restrict__ out) {
    __shared__ float red[2];
    int m = blockIdx.x, f = threadIdx.x;  // 64 threads
    float s = b1_[f];
    #pragma unroll 4
    for (int k = 0; k < 128; k++)
        s = fmaf(g_mol[m * 128 + k], w1[k * 64 + f], s);
    float v = sspf(s) * w2[f];
    #pragma unroll
    for (int o = 16; o; o >>= 1) v += __shfl_xor_sync(0xffffffffu, v, o);
    if ((f & 31) == 0) red[f >> 5] = v;
    __syncthreads();
    if (f == 0) out[m] = red[0] + red[1] + b2_[0];
}

// ---------------- launch ----------------------------------------------------
extern "C" void kernel_launch(void* const* d_in, const int* in_sizes, int n_in,
                              void* d_out, int out_size) {
    const int*   z    = (const int*)  d_in[0];
    const float* pos  = (const float*)d_in[1];
    const int*   erow = (const int*)  d_in[2];
    const int*   ecol = (const int*)  d_in[3];
    const int*   a2c  = (const int*)  d_in[4];
    const int*   c2m  = (const int*)  d_in[5];
    const float* emb  = (const float*)d_in[6];
    const float* mw1  = (const float*)d_in[7];
    const float* mb1  = (const float*)d_in[8];
    const float* mw2  = (const float*)d_in[9];
    const float* mb2  = (const float*)d_in[10];
    const float* cl1  = (const float*)d_in[11];
    const float* cl2  = (const float*)d_in[12];
    const float* cl2b = (const float*)d_in[13];
    const float* ilw  = (const float*)d_in[14];
    const float* ilb  = (const float*)d_in[15];
    const float* l1w  = (const float*)d_in[16];
    const float* l1b  = (const float*)d_in[17];
    const float* l2w  = (const float*)d_in[18];
    const float* l2b  = (const float*)d_in[19];
    const float* hw1  = (const float*)d_in[20];
    const float* hb1  = (const float*)d_in[21];
    const float* hw2  = (const float*)d_in[22];
    const float* hb2  = (const float*)d_in[23];
    float* out = (float*)d_out;

    const int EDGE_SMEM = EDGE_SMEM_FLOATS * 4;  // 199424 B
    cudaFuncSetAttribute(edge_kernel, cudaFuncAttributeMaxDynamicSharedMemorySize, EDGE_SMEM);
    cudaFuncSetAttribute(gemm_tc, cudaFuncAttributeMaxDynamicSharedMemorySize, GEMM_TC_SMEM);
    cudaFuncSetAttribute(gemm2_tc<true>,  cudaFuncAttributeMaxDynamicSharedMemorySize, GEMM2_SMEM);
    cudaFuncSetAttribute(gemm2_tc<false>, cudaFuncAttributeMaxDynamicSharedMemorySize, GEMM2_SMEM);

    float *ph, *pxf, *pagg, *pconf, *pmol;
    cudaGetSymbolAddress((void**)&ph,   g_h);
    cudaGetSymbolAddress((void**)&pxf,  g_xf);
    cudaGetSymbolAddress((void**)&pagg, g_agg);
    cudaGetSymbolAddress((void**)&pconf, g_conf);
    cudaGetSymbolAddress((void**)&pmol,  g_mol);

    const int GEMM_BLOCKS = (NN + 127) / 128;  // 391

    embed_kernel<<<(NN * HH + 255) / 256, 256>>>(z, emb);
    geom_kernel<<<(EE + 255) / 256, 256>>>(pos, erow, ecol);

    for (int i = 0; i < LL; i++) {
        gemm_tc<<<GEMM_BLOCKS, GT, GEMM_TC_SMEM>>>(ph, cl1 + (size_t)i * HH * NFF, pxf, NN);
        cudaMemsetAsync(pagg, 0, (size_t)NN * HH * sizeof(float));
        edge_kernel<<<152, ETHREADS, EDGE_SMEM>>>(mw1 + (size_t)i * GG * NFF,
                                                  mb1 + (size_t)i * NFF,
                                                  mw2 + (size_t)i * NFF * NFF,
                                                  mb2 + (size_t)i * NFF,
                                                  erow, ecol, pxf, pagg);
        // fused: x = agg@cl2 + b ; h = h + ssp(x)@ilw + b
        gemm2_tc<true><<<GEMM_BLOCKS, GT, GEMM2_SMEM>>>(pagg,
                                                        cl2 + (size_t)i * NFF * HH,
                                                        cl2b + (size_t)i * HH,
                                                        ilw + (size_t)i * HH * HH,
                                                        ilb + (size_t)i * HH,
                                                        ph, ph, NN);
    }

    // final fused: h2 = ssp(h@lin1 + b)@lin2 + b -> g_xf
    gemm2_tc<false><<<GEMM_BLOCKS, GT, GEMM2_SMEM>>>(ph, l1w, l1b, l2w, l2b,
                                                     nullptr, pxf, NN);

    cudaMemsetAsync(pconf, 0, (size_t)NCC * HH * sizeof(float));
    cudaMemsetAsync(pmol,  0, (size_t)NMM * HH * sizeof(float));
    pool1_kernel<<<(NN * 32 + 255) / 256, 256>>>(a2c, pxf);
    pool2_kernel<<<(NCC * 32 + 255) / 256, 256>>>(c2m);
    head_kernel<<<NMM, 64>>>(hw1, hb1, hw2, hb2, out);
}